// round 3
// baseline (speedup 1.0000x reference)
#include <cuda_runtime.h>

// Problem constants
#define BATCH 32
#define CIN   64
#define HID   384
#define RED   16
#define COUT  64
#define HS    56
#define HW    3136              // 56*56
#define NPIX  (BATCH*HW)        // 100352
#define KEXP  (CIN*9)           // 576

// Scratch (allocation-free: __device__ globals)
__device__ float g_h[BATCH*HID*HW];     // after expand conv + BN + SiLU
__device__ float g_d[BATCH*HID*HW];     // after depthwise + BN + SiLU
__device__ float g_pool[BATCH*HID];     // global average pool of g_d
__device__ float g_s[BATCH*HID];        // SE gate
__device__ float g_sc1[HID], g_sh1[HID];
__device__ float g_sc2[HID], g_sh2[HID];
__device__ float g_sc3[COUT], g_sh3[COUT];

__device__ __forceinline__ float silu_f(float v)    { return v / (1.f + __expf(-v)); }
__device__ __forceinline__ float sigmoid_f(float v) { return 1.f / (1.f + __expf(-v)); }

// ---------------------------------------------------------------------------
// Kernel 0: fold BN params into per-channel scale/shift
// ---------------------------------------------------------------------------
__global__ void bn_prep_kernel(
    const float* __restrict__ g1, const float* __restrict__ b1,
    const float* __restrict__ m1, const float* __restrict__ v1,
    const float* __restrict__ g2, const float* __restrict__ b2,
    const float* __restrict__ m2, const float* __restrict__ v2,
    const float* __restrict__ g3, const float* __restrict__ b3,
    const float* __restrict__ m3, const float* __restrict__ v3)
{
    int t = threadIdx.x;
    if (t < HID) {
        float s1 = g1[t] * rsqrtf(v1[t] + 1e-5f);
        g_sc1[t] = s1; g_sh1[t] = b1[t] - m1[t] * s1;
        float s2 = g2[t] * rsqrtf(v2[t] + 1e-5f);
        g_sc2[t] = s2; g_sh2[t] = b2[t] - m2[t] * s2;
    }
    if (t < COUT) {
        float s3 = g3[t] * rsqrtf(v3[t] + 1e-5f);
        g_sc3[t] = s3; g_sh3[t] = b3[t] - m3[t] * s3;
    }
}

// ---------------------------------------------------------------------------
// Kernel 1: expand conv 3x3 (64->384) as implicit GEMM, fused BN1 + SiLU
//   C[384, 100352] = W[384, 576] @ im2col(x)[576, 100352]
//   Block tile 128x128, K-step 8, 256 threads, 8x8 per-thread microtile.
//   Software-pipelined: next K-slab prefetched into registers during compute.
// ---------------------------------------------------------------------------
__global__ __launch_bounds__(256, 2)
void expand_conv_kernel(const float* __restrict__ x, const float* __restrict__ w)
{
    __shared__ float As[8][128];   // As[k][m]
    __shared__ float Bs[8][128];   // Bs[k][n]

    const int tid = threadIdx.x;
    const int tx = tid & 15;       // n-dim microtile index (8 cols each)
    const int ty = tid >> 4;       // m-dim microtile index (8 rows each)
    const int m0 = blockIdx.y * 128;
    const int n0 = blockIdx.x * 128;

    // B-loader mapping: thread -> (kk, 4 consecutive n)
    const int kk = tid >> 5;              // 0..7
    const int n4 = (tid & 31) << 2;       // 0,4,...,124
    int xoff[4], boh[4], bow[4];
#pragma unroll
    for (int j = 0; j < 4; j++) {
        int ncol = n0 + n4 + j;
        int b = ncol / HW;
        int p = ncol - b * HW;
        int oh = p / HS;
        int ow = p - oh * HS;
        boh[j] = oh; bow[j] = ow;
        xoff[j] = b * (CIN * HW) + oh * HS + ow;
    }

    // A-loader mapping: thread -> (row m, 4 consecutive k)
    const int am  = tid >> 1;             // 0..127
    const int ak4 = (tid & 1) * 4;        // 0 or 4
    const float* wrow = w + (m0 + am) * KEXP + ak4;

    float acc[8][8];
#pragma unroll
    for (int i = 0; i < 8; i++)
#pragma unroll
        for (int j = 0; j < 8; j++) acc[i][j] = 0.f;

    // ---- prefetch helpers: load k-slab [k0, k0+8) into registers ----
    float4 avp;
    float  bvp[4];

    auto fetch = [&](int k0) {
        avp = *reinterpret_cast<const float4*>(wrow + k0);
        int kq = k0 + kk;
        int ic = kq / 9;
        int r  = kq - ic * 9;
        int r3 = r / 3;
        int dh = r3 - 1;
        int dw = (r - r3 * 3) - 1;
        const float* xp = x + ic * HW + dh * HS + dw;
#pragma unroll
        for (int j = 0; j < 4; j++) {
            int ih = boh[j] + dh;
            int iw = bow[j] + dw;
            bool ok = ((unsigned)ih < (unsigned)HS) && ((unsigned)iw < (unsigned)HS);
            bvp[j] = ok ? __ldg(xp + xoff[j]) : 0.f;
        }
    };

    fetch(0);

    for (int k0 = 0; k0 < KEXP; k0 += 8) {
        // --- commit prefetched slab to smem ---
        As[ak4 + 0][am] = avp.x;
        As[ak4 + 1][am] = avp.y;
        As[ak4 + 2][am] = avp.z;
        As[ak4 + 3][am] = avp.w;
        *reinterpret_cast<float4*>(&Bs[kk][n4]) =
            make_float4(bvp[0], bvp[1], bvp[2], bvp[3]);

        __syncthreads();

        // --- prefetch next slab while computing this one ---
        if (k0 + 8 < KEXP) fetch(k0 + 8);

#pragma unroll
        for (int k = 0; k < 8; k++) {
            float a[8], bf[8];
            *reinterpret_cast<float4*>(&a[0])  = *reinterpret_cast<const float4*>(&As[k][ty * 8]);
            *reinterpret_cast<float4*>(&a[4])  = *reinterpret_cast<const float4*>(&As[k][ty * 8 + 4]);
            *reinterpret_cast<float4*>(&bf[0]) = *reinterpret_cast<const float4*>(&Bs[k][tx * 8]);
            *reinterpret_cast<float4*>(&bf[4]) = *reinterpret_cast<const float4*>(&Bs[k][tx * 8 + 4]);
#pragma unroll
            for (int i = 0; i < 8; i++)
#pragma unroll
                for (int j = 0; j < 8; j++)
                    acc[i][j] = fmaf(a[i], bf[j], acc[i][j]);
        }
        __syncthreads();
    }

    // --- epilogue: BN1 + SiLU, write NCHW h ---
#pragma unroll
    for (int i = 0; i < 8; i++) {
        int oc = m0 + ty * 8 + i;
        float sc = g_sc1[oc], sh = g_sh1[oc];
#pragma unroll
        for (int j = 0; j < 8; j++) {
            int ncol = n0 + tx * 8 + j;
            int b = ncol / HW;
            int p = ncol - b * HW;
            float v = fmaf(acc[i][j], sc, sh);
            g_h[(b * HID + oc) * HW + p] = silu_f(v);
        }
    }
}

// ---------------------------------------------------------------------------
// Kernel 2: depthwise 3x3 + BN2 + SiLU, fused global-average-pool partial
//   One block per (b, c) plane.
// ---------------------------------------------------------------------------
__global__ __launch_bounds__(256)
void dw_conv_kernel(const float* __restrict__ wdw)
{
    const int bc = blockIdx.x;            // b*HID + c
    const int c  = bc % HID;
    const float* __restrict__ hp = g_h + (size_t)bc * HW;
    float* __restrict__ dp = g_d + (size_t)bc * HW;

    float w[9];
#pragma unroll
    for (int i = 0; i < 9; i++) w[i] = wdw[c * 9 + i];
    const float sc = g_sc2[c], sh = g_sh2[c];

    float lsum = 0.f;
    for (int p = threadIdx.x; p < HW; p += 256) {
        int oh = p / HS;
        int ow = p - oh * HS;
        float acc = 0.f;
#pragma unroll
        for (int kh = 0; kh < 3; kh++) {
            int ih = oh + kh - 1;
            if ((unsigned)ih < (unsigned)HS) {
#pragma unroll
                for (int kw = 0; kw < 3; kw++) {
                    int iw = ow + kw - 1;
                    if ((unsigned)iw < (unsigned)HS)
                        acc = fmaf(w[kh * 3 + kw], hp[ih * HS + iw], acc);
                }
            }
        }
        float v = silu_f(fmaf(acc, sc, sh));
        dp[p] = v;
        lsum += v;
    }

    __shared__ float red[256];
    red[threadIdx.x] = lsum;
    __syncthreads();
#pragma unroll
    for (int s = 128; s > 0; s >>= 1) {
        if (threadIdx.x < s) red[threadIdx.x] += red[threadIdx.x + s];
        __syncthreads();
    }
    if (threadIdx.x == 0) g_pool[bc] = red[0] * (1.f / (float)HW);
}

// ---------------------------------------------------------------------------
// Kernel 3: squeeze-excitation bottleneck. One block per batch element.
// ---------------------------------------------------------------------------
__global__ void se_kernel(const float* __restrict__ w1, const float* __restrict__ w2)
{
    const int b = blockIdx.x;
    const int t = threadIdx.x;            // 0..383
    __shared__ float pool[HID];
    __shared__ float s1[RED];

    pool[t] = g_pool[b * HID + t];
    __syncthreads();

    if (t < RED) {
        float acc = 0.f;
        for (int c = 0; c < HID; c++)
            acc = fmaf(w1[t * HID + c], pool[c], acc);
        s1[t] = silu_f(acc);
    }
    __syncthreads();

    float acc = 0.f;
#pragma unroll
    for (int r = 0; r < RED; r++)
        acc = fmaf(w2[t * RED + r], s1[r], acc);
    g_s[b * HID + t] = sigmoid_f(acc);
}

// ---------------------------------------------------------------------------
// Kernel 4: pointwise 1x1 (384->64) with SE scale folded into B operand,
//           fused BN3 + residual add.
//   Block tile 64x128, K-step 8, 256 threads, 4x8 microtile.
// ---------------------------------------------------------------------------
__global__ __launch_bounds__(256)
void pw_conv_kernel(const float* __restrict__ wpw, const float* __restrict__ x,
                    float* __restrict__ out)
{
    __shared__ float As[8][64];    // As[k][m]
    __shared__ float Bs[8][128];   // Bs[k][n]

    const int tid = threadIdx.x;
    const int tx = tid & 15;
    const int ty = tid >> 4;
    const int n0 = blockIdx.x * 128;

    const int kk = tid >> 5;
    const int n4 = (tid & 31) << 2;
    int jb[4], jp[4];
#pragma unroll
    for (int j = 0; j < 4; j++) {
        int ncol = n0 + n4 + j;
        int b = ncol / HW;
        jb[j] = b;
        jp[j] = ncol - b * HW;
    }

    float acc[4][8];
#pragma unroll
    for (int i = 0; i < 4; i++)
#pragma unroll
        for (int j = 0; j < 8; j++) acc[i][j] = 0.f;

    for (int k0 = 0; k0 < HID; k0 += 8) {
        // A tile: 64x8 weights, 2 elems/thread
        {
            int e = tid * 2;
#pragma unroll
            for (int q = 0; q < 2; q++) {
                int ee = e + q;
                int m  = ee >> 3;
                int kq = ee & 7;
                As[kq][m] = wpw[m * HID + k0 + kq];
            }
        }
        // B tile: d * SE-gate
        {
            int c = k0 + kk;
            float vj[4];
#pragma unroll
            for (int j = 0; j < 4; j++) {
                int bg = jb[j] * HID + c;
                vj[j] = g_d[(size_t)bg * HW + jp[j]] * g_s[bg];
            }
            *reinterpret_cast<float4*>(&Bs[kk][n4]) = make_float4(vj[0], vj[1], vj[2], vj[3]);
        }
        __syncthreads();

#pragma unroll
        for (int k = 0; k < 8; k++) {
            float a[4], bf[8];
            *reinterpret_cast<float4*>(&a[0])  = *reinterpret_cast<const float4*>(&As[k][ty * 4]);
            *reinterpret_cast<float4*>(&bf[0]) = *reinterpret_cast<const float4*>(&Bs[k][tx * 8]);
            *reinterpret_cast<float4*>(&bf[4]) = *reinterpret_cast<const float4*>(&Bs[k][tx * 8 + 4]);
#pragma unroll
            for (int i = 0; i < 4; i++)
#pragma unroll
                for (int j = 0; j < 8; j++)
                    acc[i][j] = fmaf(a[i], bf[j], acc[i][j]);
        }
        __syncthreads();
    }

    // epilogue: BN3 + residual
#pragma unroll
    for (int i = 0; i < 4; i++) {
        int oc = ty * 4 + i;
        float sc = g_sc3[oc], sh = g_sh3[oc];
#pragma unroll
        for (int j = 0; j < 8; j++) {
            int ncol = n0 + tx * 8 + j;
            int b = ncol / HW;
            int p = ncol - b * HW;
            int idx = (b * COUT + oc) * HW + p;
            out[idx] = fmaf(acc[i][j], sc, sh) + x[idx];
        }
    }
}

// ---------------------------------------------------------------------------
// Launch
// ---------------------------------------------------------------------------
extern "C" void kernel_launch(void* const* d_in, const int* in_sizes, int n_in,
                              void* d_out, int out_size)
{
    const float* x     = (const float*)d_in[0];
    const float* w_exp = (const float*)d_in[1];
    const float* g1 = (const float*)d_in[2];
    const float* b1 = (const float*)d_in[3];
    const float* m1 = (const float*)d_in[4];
    const float* v1 = (const float*)d_in[5];
    const float* w_dw = (const float*)d_in[6];
    const float* g2 = (const float*)d_in[7];
    const float* b2 = (const float*)d_in[8];
    const float* m2 = (const float*)d_in[9];
    const float* v2 = (const float*)d_in[10];
    const float* w_se1 = (const float*)d_in[11];
    const float* w_se2 = (const float*)d_in[12];
    const float* w_pw  = (const float*)d_in[13];
    const float* g3 = (const float*)d_in[14];
    const float* b3 = (const float*)d_in[15];
    const float* m3 = (const float*)d_in[16];
    const float* v3 = (const float*)d_in[17];
    float* out = (float*)d_out;

    bn_prep_kernel<<<1, HID>>>(g1, b1, m1, v1, g2, b2, m2, v2, g3, b3, m3, v3);
    expand_conv_kernel<<<dim3(NPIX / 128, HID / 128), 256>>>(x, w_exp);
    dw_conv_kernel<<<BATCH * HID, 256>>>(w_dw);
    se_kernel<<<BATCH, HID>>>(w_se1, w_se2);
    pw_conv_kernel<<<NPIX / 128, 256>>>(w_pw, x, out);
}

// round 7
// speedup vs baseline: 2.9450x; 2.9450x over previous
#include <cuda_runtime.h>
#include <cstdint>

// Problem constants
#define BATCH 32
#define CIN   64
#define HID   384
#define RED   16
#define COUT  64
#define HS    56
#define HW    3136              // 56*56
#define NPIX  (BATCH*HW)        // 100352
#define KEXP  (CIN*9)           // 576

// Scratch (allocation-free: __device__ globals)
__device__ float g_h[BATCH*HID*HW];     // after expand conv + BN + SiLU
__device__ float g_d[BATCH*HID*HW];     // after depthwise + BN + SiLU
__device__ float g_pool[BATCH*HID];     // global average pool of g_d
__device__ float g_s[BATCH*HID];        // SE gate
__device__ float g_sc1[HID], g_sh1[HID];
__device__ float g_sc2[HID], g_sh2[HID];
__device__ float g_sc3[COUT], g_sh3[COUT];

__device__ __forceinline__ float silu_f(float v)    { return v / (1.f + __expf(-v)); }
__device__ __forceinline__ float sigmoid_f(float v) { return 1.f / (1.f + __expf(-v)); }

__device__ __forceinline__ uint32_t f32_to_tf32(float f) {
    uint32_t o;
    asm("cvt.rna.tf32.f32 %0, %1;" : "=r"(o) : "f"(f));
    return o;
}

// mma.sync m16n8k8 tf32: D[16x8] += A[16x8] * B[8x8]
__device__ __forceinline__ void mma_tf32(float* c, const uint32_t* a, const uint32_t* b) {
    asm volatile(
        "mma.sync.aligned.m16n8k8.row.col.f32.tf32.tf32.f32 "
        "{%0,%1,%2,%3}, {%4,%5,%6,%7}, {%8,%9}, {%0,%1,%2,%3};"
        : "+f"(c[0]), "+f"(c[1]), "+f"(c[2]), "+f"(c[3])
        : "r"(a[0]), "r"(a[1]), "r"(a[2]), "r"(a[3]), "r"(b[0]), "r"(b[1]));
}

// ---------------------------------------------------------------------------
// Kernel 0: fold BN params into per-channel scale/shift
// ---------------------------------------------------------------------------
__global__ void bn_prep_kernel(
    const float* __restrict__ g1, const float* __restrict__ b1,
    const float* __restrict__ m1, const float* __restrict__ v1,
    const float* __restrict__ g2, const float* __restrict__ b2,
    const float* __restrict__ m2, const float* __restrict__ v2,
    const float* __restrict__ g3, const float* __restrict__ b3,
    const float* __restrict__ m3, const float* __restrict__ v3)
{
    int t = threadIdx.x;
    if (t < HID) {
        float s1 = g1[t] * rsqrtf(v1[t] + 1e-5f);
        g_sc1[t] = s1; g_sh1[t] = b1[t] - m1[t] * s1;
        float s2 = g2[t] * rsqrtf(v2[t] + 1e-5f);
        g_sc2[t] = s2; g_sh2[t] = b2[t] - m2[t] * s2;
    }
    if (t < COUT) {
        float s3 = g3[t] * rsqrtf(v3[t] + 1e-5f);
        g_sc3[t] = s3; g_sh3[t] = b3[t] - m3[t] * s3;
    }
}

// ---------------------------------------------------------------------------
// Kernel 1: expand conv 3x3 (64->384) via tensor-core mma.sync (tf32),
//           fused BN1 + SiLU.
//   GEMM: C[384, 100352] = W[384, 576] @ im2col(x)[576, 100352]
//   Block tile M=128 x N=128, 8 warps (4x2), warp tile 32x64, K-step 8.
//   Smem row stride 136 floats -> conflict-free fragment LDS (bank = 8t+g).
// ---------------------------------------------------------------------------
#define PADK 136

__global__ __launch_bounds__(256, 2)
void expand_conv_mma_kernel(const float* __restrict__ x, const float* __restrict__ w)
{
    __shared__ float As[8][PADK];   // As[k][m] (tf32 bit patterns)
    __shared__ float Bs[8][PADK];   // Bs[k][n]

    const int tid = threadIdx.x;
    const int wid = tid >> 5;
    const int lid = tid & 31;
    const int g   = lid >> 2;       // 0..7
    const int t   = lid & 3;        // 0..3
    const int wm  = (wid >> 1) * 32;    // warp m-offset within 128
    const int wn  = (wid & 1) * 64;     // warp n-offset within 128
    const int m0  = blockIdx.y * 128;
    const int n0  = blockIdx.x * 128;

    // --- B-loader mapping: thread -> (k-row kk, 4 consecutive n) ---
    const int kk = tid >> 5;               // 0..7
    const int n4 = (lid) << 2;             // 0..124
    int xoff[4], boh[4], bow[4];
#pragma unroll
    for (int j = 0; j < 4; j++) {
        int ncol = n0 + n4 + j;
        int b = ncol / HW;
        int p = ncol - b * HW;
        int oh = p / HS;
        int ow = p - oh * HS;
        boh[j] = oh; bow[j] = ow;
        xoff[j] = b * (CIN * HW) + oh * HS + ow;
    }

    // --- A-loader mapping: thread -> (row am, 4 consecutive k) ---
    const int am  = tid >> 1;              // 0..127
    const int ak4 = (tid & 1) * 4;         // 0 or 4
    const float* wrow = w + (size_t)(m0 + am) * KEXP + ak4;

    float acc[2][8][4];
#pragma unroll
    for (int i = 0; i < 2; i++)
#pragma unroll
        for (int j = 0; j < 8; j++)
#pragma unroll
            for (int q = 0; q < 4; q++) acc[i][j][q] = 0.f;

    // ---- register prefetch of k-slab [k0, k0+8) ----
    float4 avp;
    float  bvp[4];
    auto fetch = [&](int k0) {
        avp = *reinterpret_cast<const float4*>(wrow + k0);
        int kq = k0 + kk;
        int ic = kq / 9;
        int r  = kq - ic * 9;
        int r3 = r / 3;
        int dh = r3 - 1;
        int dw = (r - r3 * 3) - 1;
        const float* xp = x + ic * HW + dh * HS + dw;
#pragma unroll
        for (int j = 0; j < 4; j++) {
            int ih = boh[j] + dh;
            int iw = bow[j] + dw;
            bool ok = ((unsigned)ih < (unsigned)HS) && ((unsigned)iw < (unsigned)HS);
            bvp[j] = ok ? __ldg(xp + xoff[j]) : 0.f;
        }
    };

    fetch(0);

    for (int k0 = 0; k0 < KEXP; k0 += 8) {
        // --- commit prefetched slab to smem (as tf32 bit patterns) ---
        As[ak4 + 0][am] = __uint_as_float(f32_to_tf32(avp.x));
        As[ak4 + 1][am] = __uint_as_float(f32_to_tf32(avp.y));
        As[ak4 + 2][am] = __uint_as_float(f32_to_tf32(avp.z));
        As[ak4 + 3][am] = __uint_as_float(f32_to_tf32(avp.w));
#pragma unroll
        for (int j = 0; j < 4; j++)
            Bs[kk][n4 + j] = __uint_as_float(f32_to_tf32(bvp[j]));
        __syncthreads();

        if (k0 + 8 < KEXP) fetch(k0 + 8);

        // --- load fragments and issue 16 mma ---
        uint32_t afr[2][4];
#pragma unroll
        for (int fm = 0; fm < 2; fm++) {
            int mb = wm + fm * 16;
            afr[fm][0] = __float_as_uint(As[t][mb + g]);
            afr[fm][1] = __float_as_uint(As[t][mb + g + 8]);
            afr[fm][2] = __float_as_uint(As[t + 4][mb + g]);
            afr[fm][3] = __float_as_uint(As[t + 4][mb + g + 8]);
        }
#pragma unroll
        for (int fn = 0; fn < 8; fn++) {
            uint32_t bfr[2];
            int nb = wn + fn * 8;
            bfr[0] = __float_as_uint(Bs[t][nb + g]);
            bfr[1] = __float_as_uint(Bs[t + 4][nb + g]);
            mma_tf32(acc[0][fn], afr[0], bfr);
            mma_tf32(acc[1][fn], afr[1], bfr);
        }
        __syncthreads();
    }

    // --- epilogue: BN1 + SiLU, write NCHW h ---
    // c0:(g,2t) c1:(g,2t+1) c2:(g+8,2t) c3:(g+8,2t+1)
#pragma unroll
    for (int fm = 0; fm < 2; fm++) {
#pragma unroll
        for (int half = 0; half < 2; half++) {
            int oc = m0 + wm + fm * 16 + g + half * 8;
            float sc = g_sc1[oc], sh = g_sh1[oc];
#pragma unroll
            for (int fn = 0; fn < 8; fn++) {
#pragma unroll
                for (int e = 0; e < 2; e++) {
                    int ncol = n0 + wn + fn * 8 + 2 * t + e;
                    int b = ncol / HW;
                    int p = ncol - b * HW;
                    float v = fmaf(acc[fm][fn][half * 2 + e], sc, sh);
                    g_h[((size_t)b * HID + oc) * HW + p] = silu_f(v);
                }
            }
        }
    }
}

// ---------------------------------------------------------------------------
// Kernel 2: depthwise 3x3 + BN2 + SiLU, fused global-average-pool partial
// ---------------------------------------------------------------------------
__global__ __launch_bounds__(256)
void dw_conv_kernel(const float* __restrict__ wdw)
{
    const int bc = blockIdx.x;            // b*HID + c
    const int c  = bc % HID;
    const float* __restrict__ hp = g_h + (size_t)bc * HW;
    float* __restrict__ dp = g_d + (size_t)bc * HW;

    float w[9];
#pragma unroll
    for (int i = 0; i < 9; i++) w[i] = wdw[c * 9 + i];
    const float sc = g_sc2[c], sh = g_sh2[c];

    float lsum = 0.f;
    for (int p = threadIdx.x; p < HW; p += 256) {
        int oh = p / HS;
        int ow = p - oh * HS;
        float acc = 0.f;
#pragma unroll
        for (int kh = 0; kh < 3; kh++) {
            int ih = oh + kh - 1;
            if ((unsigned)ih < (unsigned)HS) {
#pragma unroll
                for (int kw = 0; kw < 3; kw++) {
                    int iw = ow + kw - 1;
                    if ((unsigned)iw < (unsigned)HS)
                        acc = fmaf(w[kh * 3 + kw], hp[ih * HS + iw], acc);
                }
            }
        }
        float v = silu_f(fmaf(acc, sc, sh));
        dp[p] = v;
        lsum += v;
    }

    __shared__ float red[256];
    red[threadIdx.x] = lsum;
    __syncthreads();
#pragma unroll
    for (int s = 128; s > 0; s >>= 1) {
        if (threadIdx.x < s) red[threadIdx.x] += red[threadIdx.x + s];
        __syncthreads();
    }
    if (threadIdx.x == 0) g_pool[bc] = red[0] * (1.f / (float)HW);
}

// ---------------------------------------------------------------------------
// Kernel 3: squeeze-excitation bottleneck. One block per batch element.
// ---------------------------------------------------------------------------
__global__ void se_kernel(const float* __restrict__ w1, const float* __restrict__ w2)
{
    const int b = blockIdx.x;
    const int t = threadIdx.x;            // 0..383
    __shared__ float pool[HID];
    __shared__ float s1[RED];

    pool[t] = g_pool[b * HID + t];
    __syncthreads();

    if (t < RED) {
        float acc = 0.f;
        for (int c = 0; c < HID; c++)
            acc = fmaf(w1[t * HID + c], pool[c], acc);
        s1[t] = silu_f(acc);
    }
    __syncthreads();

    float acc = 0.f;
#pragma unroll
    for (int r = 0; r < RED; r++)
        acc = fmaf(w2[t * RED + r], s1[r], acc);
    g_s[b * HID + t] = sigmoid_f(acc);
}

// ---------------------------------------------------------------------------
// Kernel 4: pointwise 1x1 (384->64) with SE scale folded into B operand,
//           fused BN3 + residual add. SIMT GEMM.
// ---------------------------------------------------------------------------
__global__ __launch_bounds__(256)
void pw_conv_kernel(const float* __restrict__ wpw, const float* __restrict__ x,
                    float* __restrict__ out)
{
    __shared__ float As[8][64];    // As[k][m]
    __shared__ float Bs[8][128];   // Bs[k][n]

    const int tid = threadIdx.x;
    const int tx = tid & 15;
    const int ty = tid >> 4;
    const int n0 = blockIdx.x * 128;

    const int kk = tid >> 5;
    const int n4 = (tid & 31) << 2;
    int jb[4], jp[4];
#pragma unroll
    for (int j = 0; j < 4; j++) {
        int ncol = n0 + n4 + j;
        int b = ncol / HW;
        jb[j] = b;
        jp[j] = ncol - b * HW;
    }

    float acc[4][8];
#pragma unroll
    for (int i = 0; i < 4; i++)
#pragma unroll
        for (int j = 0; j < 8; j++) acc[i][j] = 0.f;

    for (int k0 = 0; k0 < HID; k0 += 8) {
        {
            int e = tid * 2;
#pragma unroll
            for (int q = 0; q < 2; q++) {
                int ee = e + q;
                int m  = ee >> 3;
                int kq = ee & 7;
                As[kq][m] = wpw[m * HID + k0 + kq];
            }
        }
        {
            int c = k0 + kk;
            float vj[4];
#pragma unroll
            for (int j = 0; j < 4; j++) {
                int bg = jb[j] * HID + c;
                vj[j] = g_d[(size_t)bg * HW + jp[j]] * g_s[bg];
            }
            *reinterpret_cast<float4*>(&Bs[kk][n4]) = make_float4(vj[0], vj[1], vj[2], vj[3]);
        }
        __syncthreads();

#pragma unroll
        for (int k = 0; k < 8; k++) {
            float a[4], bf[8];
            *reinterpret_cast<float4*>(&a[0])  = *reinterpret_cast<const float4*>(&As[k][ty * 4]);
            *reinterpret_cast<float4*>(&bf[0]) = *reinterpret_cast<const float4*>(&Bs[k][tx * 8]);
            *reinterpret_cast<float4*>(&bf[4]) = *reinterpret_cast<const float4*>(&Bs[k][tx * 8 + 4]);
#pragma unroll
            for (int i = 0; i < 4; i++)
#pragma unroll
                for (int j = 0; j < 8; j++)
                    acc[i][j] = fmaf(a[i], bf[j], acc[i][j]);
        }
        __syncthreads();
    }

#pragma unroll
    for (int i = 0; i < 4; i++) {
        int oc = ty * 4 + i;
        float sc = g_sc3[oc], sh = g_sh3[oc];
#pragma unroll
        for (int j = 0; j < 8; j++) {
            int ncol = n0 + tx * 8 + j;
            int b = ncol / HW;
            int p = ncol - b * HW;
            int idx = (b * COUT + oc) * HW + p;
            out[idx] = fmaf(acc[i][j], sc, sh) + x[idx];
        }
    }
}

// ---------------------------------------------------------------------------
// Launch
// ---------------------------------------------------------------------------
extern "C" void kernel_launch(void* const* d_in, const int* in_sizes, int n_in,
                              void* d_out, int out_size)
{
    const float* x     = (const float*)d_in[0];
    const float* w_exp = (const float*)d_in[1];
    const float* g1 = (const float*)d_in[2];
    const float* b1 = (const float*)d_in[3];
    const float* m1 = (const float*)d_in[4];
    const float* v1 = (const float*)d_in[5];
    const float* w_dw = (const float*)d_in[6];
    const float* g2 = (const float*)d_in[7];
    const float* b2 = (const float*)d_in[8];
    const float* m2 = (const float*)d_in[9];
    const float* v2 = (const float*)d_in[10];
    const float* w_se1 = (const float*)d_in[11];
    const float* w_se2 = (const float*)d_in[12];
    const float* w_pw  = (const float*)d_in[13];
    const float* g3 = (const float*)d_in[14];
    const float* b3 = (const float*)d_in[15];
    const float* m3 = (const float*)d_in[16];
    const float* v3 = (const float*)d_in[17];
    float* out = (float*)d_out;

    bn_prep_kernel<<<1, HID>>>(g1, b1, m1, v1, g2, b2, m2, v2, g3, b3, m3, v3);
    expand_conv_mma_kernel<<<dim3(NPIX / 128, HID / 128), 256>>>(x, w_exp);
    dw_conv_kernel<<<BATCH * HID, 256>>>(w_dw);
    se_kernel<<<BATCH, HID>>>(w_se1, w_se2);
    pw_conv_kernel<<<NPIX / 128, 256>>>(w_pw, x, out);
}